// round 3
// baseline (speedup 1.0000x reference)
#include <cuda_runtime.h>
#include <math.h>
#include <stdint.h>
#include <stddef.h>

// DBN beat decoder, persistent-delta chunked Viterbi.
// tau = 28..109 (82 tempi), S = 5617, B = 4, T = 6000.
#define NI      82
#define TROW    84        // trans_t row stride (i-major, j contiguous)
#define LROW    84
#define S_TOT   5617
#define S_PAD   5632
#define T_LEN   6000
#define BATCH   4
#define TPB     1024
#define CHUNK   28
#define NFULL   214       // full chunks cover t = 1..5992
#define ABN     640       // A/B warp group
#define CN      384       // C warp group
#define NTOPS   2296      // 82*28
#define NMAIN   3321      // states with p >= 28

__device__ float g_L[(size_t)BATCH * T_LEN * NI];   // exact L values for lazy backtrace

__device__ __forceinline__ int first_of(int j) { return 28 * j + (j * (j - 1)) / 2; }
__device__ __forceinline__ int last_of(int j)  { return first_of(j) + 27 + j; }

__global__ __launch_bounds__(TPB, 1)
void dbn_kernel(const float* __restrict__ logit, float* __restrict__ out)
{
    extern __shared__ char smraw[];
    float* trans_t = (float*)smraw;                 // [84][84]: trans_t[i][j] = trans_log[i][j]
    float* dbuf    = trans_t + TROW * TROW;         // [2][5632] persistent delta (double buf)
    float* Lbuf    = dbuf + 2 * S_PAD;              // [28][84]
    float* Fbuf    = Lbuf + CHUNK * LROW;           // [28][84]
    float* blp     = Fbuf + CHUNK * LROW;           // 6000
    float* nlp     = blp + T_LEN;                   // 6000
    float* redv    = nlp + T_LEN;                   // 32
    int*   redi    = (int*)(redv + 32);             // 32
    int*   cidx    = redi + 32;                     // 3328 (state ids with p>=28)
    unsigned char* isf = (unsigned char*)(cidx + 3328);  // 5632

    const int tid = threadIdx.x;
    const int b   = blockIdx.x;
    const float* lg = logit + (size_t)b * T_LEN;
    float* Lg   = g_L + (size_t)b * T_LEN * NI;
    float* outb = out + (size_t)b * T_LEN;

    // ================= setup =================
    if (tid < NI) {               // row i = tid of trans_log (fp64, matches numpy)
        double ti = (double)(28 + tid);
        double sum = 0.0;
        for (int jj = 0; jj < NI; ++jj)
            sum += exp(-100.0 * fabs((double)(28 + jj) / ti - 1.0));
        double ls = log(sum);
        for (int jj = 0; jj < NI; ++jj) {
            double r = -100.0 * fabs((double)(28 + jj) / ti - 1.0);
            trans_t[tid * TROW + jj] = (float)(r - ls);
        }
        trans_t[tid * TROW + 82] = -1e30f;
        trans_t[tid * TROW + 83] = -1e30f;
    }
    for (int s = tid; s < S_PAD; s += TPB) isf[s] = 0;
    for (int t = tid; t < T_LEN; t += TPB) {
        float x  = lg[t];
        float l1 = log1pf(expf(-fabsf(x)));
        blp[t] = fminf(x, 0.0f) - l1;
        nlp[t] = fminf(-x, 0.0f) - l1;
    }
    // cidx: block j contributes j states (p = 28..tau-1), offset j(j-1)/2
    for (int k = tid; k < NMAIN; k += TPB) {
        int j = (int)((1.0 + sqrt(8.0 * (double)k + 1.0)) * 0.5);
        while ((j * (j + 1)) / 2 <= k) ++j;
        while ((j * (j - 1)) / 2 > k)  --j;
        int m = k - (j * (j - 1)) / 2;
        cidx[k] = first_of(j) + 28 + m;
    }
    __syncthreads();
    if (tid < NI) isf[first_of(tid)] = 1;
    __syncthreads();

    const float logS = logf((float)S_TOT);
    for (int s = tid; s < S_TOT; s += TPB)
        dbuf[s] = (isf[s] ? blp[0] : nlp[0]) - logS;
    __syncthreads();

    // ================= 214 full chunks =================
    for (int c = 0; c < NFULL; ++c) {
        const int t0 = 1 + CHUNK * c;
        const float* dprev = dbuf + (c & 1) * S_PAD;
        float*       dnew  = dbuf + ((c + 1) & 1) * S_PAD;

        if (tid < ABN) {
            // ---- Phase A: L[g][j] = dprev[last_j - g] + nlp[t0..t0+g-1] ----
            for (int task = tid; task < NTOPS; task += ABN) {
                int g = task / NI;
                int j = task - g * NI;
                float acc = dprev[last_of(j) - g];
                const float* np = nlp + t0;
#pragma unroll 4
                for (int k = 0; k < g; ++k) acc += np[k];
                Lbuf[g * LROW + j] = acc;
                Lg[(size_t)(t0 + g) * NI + j] = acc;
            }
            asm volatile("bar.sync 1, %0;" :: "r"(ABN) : "memory");

            // ---- Phase B: F[f][j] = max_i(L[f][i]+trans[i][j]) + blp[t0+f] ----
            if (tid < 588) {
                int f  = tid / 21;
                int jt = tid - f * 21;
                const float* Lrow = Lbuf + f * LROW;
                const float4* tc  = (const float4*)(trans_t + 4 * jt);
                float mx = -1e30f, my = -1e30f, mz = -1e30f, mw = -1e30f;
#pragma unroll 2
                for (int i = 0; i < NI; ++i) {
                    float  lv = Lrow[i];
                    float4 tv = tc[i * (TROW / 4)];
                    mx = fmaxf(mx, lv + tv.x);
                    my = fmaxf(my, lv + tv.y);
                    mz = fmaxf(mz, lv + tv.z);
                    mw = fmaxf(mw, lv + tv.w);
                }
                float bt = blp[t0 + f];
                int j0 = 4 * jt;
                Fbuf[f * LROW + j0]     = mx + bt;
                Fbuf[f * LROW + j0 + 1] = my + bt;
                if (j0 + 2 < NI) {
                    Fbuf[f * LROW + j0 + 2] = mz + bt;
                    Fbuf[f * LROW + j0 + 3] = mw + bt;
                }
            }
        } else {
            // ---- Phase C-main: p >= 28 states, register-resident emissions ----
            float nr[CHUNK];
#pragma unroll
            for (int k = 0; k < CHUNK; ++k) nr[k] = nlp[t0 + k];
            for (int k = tid - ABN; k < NMAIN; k += CN) {
                int s = cidx[k];
                float acc = dprev[s - CHUNK];
#pragma unroll
                for (int k2 = 0; k2 < CHUNK; ++k2) acc += nr[k2];
                dnew[s] = acc;
            }
        }
        __syncthreads();

        // ---- Phase C-top: p <= 27 states from this chunk's F ----
        for (int q = tid; q < NTOPS; q += TPB) {
            int j = q / CHUNK;
            int p = q - j * CHUNK;
            float acc = Fbuf[(CHUNK - 1 - p) * LROW + j];
            const float* np = nlp + t0;
#pragma unroll 4
            for (int k = CHUNK - p; k < CHUNK; ++k) acc += np[k];
            dnew[first_of(j) + p] = acc;
        }
        __syncthreads();
    }

    // ================= partial tail: t = 5993..5999 (7 frames) =================
    int ping = NFULL & 1;   // buffer holding delta at t=5992
    for (int t = 1 + CHUNK * NFULL; t < T_LEN; ++t) {
        const float* dprev = dbuf + ping * S_PAD;
        float*       dnew  = dbuf + (ping ^ 1) * S_PAD;
        if (tid < NI) {
            float lv = dprev[last_of(tid)];
            Lbuf[tid] = lv;
            Lg[(size_t)t * NI + tid] = lv;
        }
        __syncthreads();
        if (tid < NI) {
            float m = -1e30f;
            for (int i = 0; i < NI; ++i)
                m = fmaxf(m, Lbuf[i] + trans_t[i * TROW + tid]);
            dnew[first_of(tid)] = m + blp[t];
        } else if (tid >= 128) {
            float nb = nlp[t];
            for (int s = tid - 128; s < S_TOT; s += TPB - 128)
                if (!isf[s]) dnew[s] = dprev[s - 1] + nb;
        }
        __syncthreads();
        ping ^= 1;
    }

    // ================= final argmax (first-max = smallest s) =================
    const float* df = dbuf + ping * S_PAD;
    for (int t = tid; t < T_LEN; t += TPB) outb[t] = 0.0f;

    float bv = -INFINITY; int bs = 0x7fffffff;
    for (int s = tid; s < S_TOT; s += TPB) {
        float v = df[s];
        if (v > bv) { bv = v; bs = s; }
    }
#pragma unroll
    for (int off = 16; off; off >>= 1) {
        float ov = __shfl_xor_sync(0xffffffffu, bv, off);
        int   oi = __shfl_xor_sync(0xffffffffu, bs, off);
        if (ov > bv || (ov == bv && oi < bs)) { bv = ov; bs = oi; }
    }
    if ((tid & 31) == 0) { redv[tid >> 5] = bv; redi[tid >> 5] = bs; }
    __syncthreads();

    // ================= warp-cooperative lazy backtrace =================
    if (tid < 32) {
        bv = redv[tid]; bs = redi[tid];
#pragma unroll
        for (int off = 16; off; off >>= 1) {
            float ov = __shfl_xor_sync(0xffffffffu, bv, off);
            int   oi = __shfl_xor_sync(0xffffffffu, bs, off);
            if (ov > bv || (ov == bv && oi < bs)) { bv = ov; bs = oi; }
        }
        int lo = 0, hi = 81;
        while (lo < hi) { int mid = (lo + hi + 1) >> 1; if (first_of(mid) <= bs) lo = mid; else hi = mid - 1; }
        int j   = lo;
        int pos = bs - first_of(j);
        int t   = T_LEN - 1;
        const int lane = tid;

        while (true) {
            int te = t - pos;
            if (te < 0) break;
            if (lane == 0) {
                float x  = lg[te];
                float sg = 1.0f / (1.0f + expf(-x));
                if (sg >= 0.05f) outb[te] = 1.0f;
            }
            if (te == 0) break;
            const float* Lr = Lg + (size_t)te * NI;
            float best = -INFINITY; int bi = 0x7fffffff;
            for (int i = lane; i < NI; i += 32) {
                float cc = Lr[i] + trans_t[i * TROW + j];
                if (cc > best) { best = cc; bi = i; }
            }
#pragma unroll
            for (int off = 16; off; off >>= 1) {
                float ov = __shfl_xor_sync(0xffffffffu, best, off);
                int   oi = __shfl_xor_sync(0xffffffffu, bi,   off);
                if (ov > best || (ov == best && oi < bi)) { best = ov; bi = oi; }
            }
            j   = bi;
            pos = 27 + j;
            t   = te - 1;
        }
    }
}

extern "C" void kernel_launch(void* const* d_in, const int* in_sizes, int n_in,
                              void* d_out, int out_size)
{
    (void)in_sizes; (void)n_in; (void)out_size;
    const float* logit = (const float*)d_in[0];
    float* out = (float*)d_out;

    const size_t smem = (size_t)(TROW * TROW + 2 * S_PAD + 2 * CHUNK * LROW
                                 + 2 * T_LEN + 32) * 4
                      + 32 * 4 + 3328 * 4 + S_PAD;
    cudaFuncSetAttribute(dbn_kernel,
                         cudaFuncAttributeMaxDynamicSharedMemorySize, (int)smem);
    dbn_kernel<<<BATCH, TPB, smem>>>(logit, out);
}

// round 4
// speedup vs baseline: 2.4344x; 2.4344x over previous
#include <cuda_runtime.h>
#include <math.h>
#include <stdint.h>
#include <stddef.h>

// DBN beat decoder, persistent-delta chunked Viterbi with ILP transposition.
// tau = 28..109 (82 tempi), S = 5617, B = 4, T = 6000.
#define NI     82
#define TROW   84       // trans_t row stride (i-major), mult of 4 for float4
#define LR     85       // Lbuf row stride (odd -> conflict-free f-strided access)
#define FR     84       // Fbuf row stride
#define S_TOT  5617
#define S_PAD  5632
#define T_LEN  6000
#define BATCH  4
#define TPB    1024
#define CHUNK  28
#define NFULL  214      // full chunks cover t = 1..5992
#define NTOPS  2296     // 28*82 (L tasks / top states)
#define NMAIN  3321     // states with p >= 28
#define BTH    294      // B threads: 21 j-quads x 14 f-pairs

__device__ float g_L[(size_t)BATCH * T_LEN * NI];   // exact L for lazy backtrace

__device__ __forceinline__ int first_of(int j) { return 28 * j + (j * (j - 1)) / 2; }
__device__ __forceinline__ int last_of(int j)  { return first_of(j) + 27 + j; }

__global__ __launch_bounds__(TPB, 1)
void dbn_kernel(const float* __restrict__ logit, float* __restrict__ out)
{
    extern __shared__ char smraw[];
    float* trans_t = (float*)smraw;                 // [84][84] trans_t[i][j]
    float* dbuf    = trans_t + TROW * TROW;         // [2][5632] persistent delta
    float* Lbuf    = dbuf + 2 * S_PAD;              // [28][85]
    float* Fbuf    = Lbuf + CHUNK * LR;             // [28][84] (16B aligned)
    float* blp     = Fbuf + CHUNK * FR;             // 6000
    float* nlp     = blp + T_LEN;                   // 6000
    float* redv    = nlp + T_LEN;                   // 32
    int*   redi    = (int*)(redv + 32);             // 32
    unsigned char* isf = (unsigned char*)(redi + 32);  // 5632

    const int tid = threadIdx.x;
    const int b   = blockIdx.x;
    const float* lg = logit + (size_t)b * T_LEN;
    float* Lg   = g_L + (size_t)b * T_LEN * NI;
    float* outb = out + (size_t)b * T_LEN;

    // ================= setup =================
    if (tid < NI) {               // trans row i = tid (fp64, matches numpy)
        double ti = (double)(28 + tid);
        double sum = 0.0;
        for (int jj = 0; jj < NI; ++jj)
            sum += exp(-100.0 * fabs((double)(28 + jj) / ti - 1.0));
        double ls = log(sum);
        for (int jj = 0; jj < NI; ++jj) {
            double r = -100.0 * fabs((double)(28 + jj) / ti - 1.0);
            trans_t[tid * TROW + jj] = (float)(r - ls);
        }
        trans_t[tid * TROW + 82] = -1e30f;
        trans_t[tid * TROW + 83] = -1e30f;
    }
    for (int s = tid; s < S_PAD; s += TPB) isf[s] = 0;
    for (int t = tid; t < T_LEN; t += TPB) {
        float x  = lg[t];
        float l1 = log1pf(expf(-fabsf(x)));
        blp[t] = fminf(x, 0.0f) - l1;
        nlp[t] = fminf(-x, 0.0f) - l1;
    }
    __syncthreads();
    if (tid < NI) isf[first_of(tid)] = 1;
    __syncthreads();

    const float logS = logf((float)S_TOT);
    for (int s = tid; s < S_TOT; s += TPB)
        dbuf[s] = (isf[s] ? blp[0] : nlp[0]) - logS;

    // ---- per-thread chunk-invariant task constants ----
    // Phase A: tasks 3*tid+m  (task = g*82 + j)
    int Ag[3], Aoff[3], Alb[3];
#pragma unroll
    for (int m = 0; m < 3; ++m) {
        int task = 3 * tid + m;
        if (task < NTOPS) {
            int g = task / NI, j = task - g * NI;
            Ag[m] = g; Aoff[m] = last_of(j) - g; Alb[m] = g * LR + j;
        } else { Ag[m] = 0; Aoff[m] = 0; Alb[m] = 0; }
    }
    // Phase C-top: tasks 3*tid+m  (task = p*82 + j)
    int Cth[3], Cfb[3], Cdn[3];
#pragma unroll
    for (int m = 0; m < 3; ++m) {
        int task = 3 * tid + m;
        if (task < NTOPS) {
            int p = task / NI, j = task - p * NI;
            Cth[m] = 28 - p; Cfb[m] = (27 - p) * FR + j; Cdn[m] = first_of(j) + p;
        } else { Cth[m] = 28; Cfb[m] = 0; Cdn[m] = 0; }
    }
    // Phase C-main (tid >= BTH): 5 states
    int Ms[5];
    if (tid >= BTH) {
#pragma unroll
        for (int m = 0; m < 5; ++m) {
            int kk = 5 * (tid - BTH) + m;
            if (kk < NMAIN) {
                int j = (int)((1.0 + sqrt(8.0 * (double)kk + 1.0)) * 0.5);
                while ((j * (j + 1)) / 2 <= kk) ++j;
                while ((j * (j - 1)) / 2 > kk)  --j;
                int mm = kk - (j * (j - 1)) / 2;
                Ms[m] = first_of(j) + 28 + mm;
            } else Ms[m] = S_PAD - 1;
        }
    }
    // Phase B (tid < BTH)
    const int jq = tid / 14;
    const int f0 = 2 * (tid - jq * 14);
    __syncthreads();

    // ================= 214 full chunks =================
    for (int c = 0; c < NFULL; ++c) {
        const int t0 = 1 + CHUNK * c;
        const float* dprev = dbuf + (c & 1) * S_PAD;
        float*       dnew  = dbuf + ((c + 1) & 1) * S_PAD;
        const float* np    = nlp + t0;
        float* Lgc = Lg + (size_t)t0 * NI;

        // ---- Phase A: L chains, 3-way ILP, predicated fused loop ----
        {
            bool v0 = (3 * tid)     < NTOPS;
            bool v1 = (3 * tid + 1) < NTOPS;
            bool v2 = (3 * tid + 2) < NTOPS;
            float a0 = v0 ? dprev[Aoff[0]] : 0.0f;
            float a1 = v1 ? dprev[Aoff[1]] : 0.0f;
            float a2 = v2 ? dprev[Aoff[2]] : 0.0f;
            int kmax = Ag[0]; if (Ag[1] > kmax) kmax = Ag[1]; if (Ag[2] > kmax) kmax = Ag[2];
#pragma unroll 4
            for (int k = 0; k < kmax; ++k) {
                float v = np[k];
                if (k < Ag[0]) a0 += v;
                if (k < Ag[1]) a1 += v;
                if (k < Ag[2]) a2 += v;
            }
            if (v0) { Lbuf[Alb[0]] = a0; Lgc[3 * tid]     = a0; }
            if (v1) { Lbuf[Alb[1]] = a1; Lgc[3 * tid + 1] = a1; }
            if (v2) { Lbuf[Alb[2]] = a2; Lgc[3 * tid + 2] = a2; }
        }
        __syncthreads();

        // ---- Phase B (tid<294) | C-main (tid>=294), concurrent ----
        if (tid < BTH) {
            const float* L0 = Lbuf + f0 * LR;
            const float* L1 = L0 + LR;
            const float4* tc = (const float4*)trans_t + jq;
            float4 A0 = make_float4(-1e30f, -1e30f, -1e30f, -1e30f);
            float4 A1 = A0;
#pragma unroll 2
            for (int i = 0; i < NI; ++i) {
                float4 tv = tc[i * (TROW / 4)];
                float l0 = L0[i];
                float l1 = L1[i];
                A0.x = fmaxf(A0.x, l0 + tv.x); A0.y = fmaxf(A0.y, l0 + tv.y);
                A0.z = fmaxf(A0.z, l0 + tv.z); A0.w = fmaxf(A0.w, l0 + tv.w);
                A1.x = fmaxf(A1.x, l1 + tv.x); A1.y = fmaxf(A1.y, l1 + tv.y);
                A1.z = fmaxf(A1.z, l1 + tv.z); A1.w = fmaxf(A1.w, l1 + tv.w);
            }
            float b0 = blp[t0 + f0], b1 = blp[t0 + f0 + 1];
            float4* F0 = (float4*)(Fbuf + f0 * FR + 4 * jq);
            float4* F1 = (float4*)(Fbuf + (f0 + 1) * FR + 4 * jq);
            *F0 = make_float4(A0.x + b0, A0.y + b0, A0.z + b0, A0.w + b0);
            *F1 = make_float4(A1.x + b1, A1.y + b1, A1.z + b1, A1.w + b1);
        } else {
            float m0 = dprev[Ms[0] - CHUNK];
            float m1 = dprev[Ms[1] - CHUNK];
            float m2 = dprev[Ms[2] - CHUNK];
            float m3 = dprev[Ms[3] - CHUNK];
            float m4 = dprev[Ms[4] - CHUNK];
#pragma unroll
            for (int k = 0; k < CHUNK; ++k) {
                float v = np[k];
                m0 += v; m1 += v; m2 += v; m3 += v; m4 += v;
            }
            int base = 5 * (tid - BTH);
            if (base     < NMAIN) dnew[Ms[0]] = m0;
            if (base + 1 < NMAIN) dnew[Ms[1]] = m1;
            if (base + 2 < NMAIN) dnew[Ms[2]] = m2;
            if (base + 3 < NMAIN) dnew[Ms[3]] = m3;
            if (base + 4 < NMAIN) dnew[Ms[4]] = m4;
        }
        __syncthreads();

        // ---- Phase C-top: p<=27 states from F, 3-way ILP ----
        {
            bool v0 = (3 * tid)     < NTOPS;
            bool v1 = (3 * tid + 1) < NTOPS;
            bool v2 = (3 * tid + 2) < NTOPS;
            float c0 = v0 ? Fbuf[Cfb[0]] : 0.0f;
            float c1 = v1 ? Fbuf[Cfb[1]] : 0.0f;
            float c2 = v2 ? Fbuf[Cfb[2]] : 0.0f;
            int kmin = Cth[0]; if (Cth[1] < kmin) kmin = Cth[1]; if (Cth[2] < kmin) kmin = Cth[2];
#pragma unroll 4
            for (int k = kmin; k < CHUNK; ++k) {
                float v = np[k];
                if (k >= Cth[0]) c0 += v;
                if (k >= Cth[1]) c1 += v;
                if (k >= Cth[2]) c2 += v;
            }
            if (v0) dnew[Cdn[0]] = c0;
            if (v1) dnew[Cdn[1]] = c1;
            if (v2) dnew[Cdn[2]] = c2;
        }
        __syncthreads();
    }

    // ================= tail frames t = 5993..5999 =================
    int ping = NFULL & 1;
    for (int t = 1 + CHUNK * NFULL; t < T_LEN; ++t) {
        const float* dprev = dbuf + ping * S_PAD;
        float*       dnew  = dbuf + (ping ^ 1) * S_PAD;
        if (tid < NI) {
            float lv = dprev[last_of(tid)];
            Lbuf[tid] = lv;
            Lg[(size_t)t * NI + tid] = lv;
        }
        __syncthreads();
        if (tid < NI) {
            float m = -1e30f;
            for (int i = 0; i < NI; ++i)
                m = fmaxf(m, Lbuf[i] + trans_t[i * TROW + tid]);
            dnew[first_of(tid)] = m + blp[t];
        } else if (tid >= 128) {
            float nb = nlp[t];
            for (int s = tid - 128; s < S_TOT; s += TPB - 128)
                if (!isf[s]) dnew[s] = dprev[s - 1] + nb;
        }
        __syncthreads();
        ping ^= 1;
    }

    // ================= final argmax (first-max = smallest s) =================
    const float* df = dbuf + ping * S_PAD;
    for (int t = tid; t < T_LEN; t += TPB) outb[t] = 0.0f;

    float bv = -INFINITY; int bs = 0x7fffffff;
    for (int s = tid; s < S_TOT; s += TPB) {
        float v = df[s];
        if (v > bv) { bv = v; bs = s; }
    }
#pragma unroll
    for (int off = 16; off; off >>= 1) {
        float ov = __shfl_xor_sync(0xffffffffu, bv, off);
        int   oi = __shfl_xor_sync(0xffffffffu, bs, off);
        if (ov > bv || (ov == bv && oi < bs)) { bv = ov; bs = oi; }
    }
    if ((tid & 31) == 0) { redv[tid >> 5] = bv; redi[tid >> 5] = bs; }
    __syncthreads();

    // ================= warp-cooperative lazy backtrace =================
    if (tid < 32) {
        bv = redv[tid]; bs = redi[tid];
#pragma unroll
        for (int off = 16; off; off >>= 1) {
            float ov = __shfl_xor_sync(0xffffffffu, bv, off);
            int   oi = __shfl_xor_sync(0xffffffffu, bs, off);
            if (ov > bv || (ov == bv && oi < bs)) { bv = ov; bs = oi; }
        }
        int lo = 0, hi = 81;
        while (lo < hi) { int mid = (lo + hi + 1) >> 1; if (first_of(mid) <= bs) lo = mid; else hi = mid - 1; }
        int j   = lo;
        int pos = bs - first_of(j);
        int t   = T_LEN - 1;
        const int lane = tid;

        while (true) {
            int te = t - pos;
            if (te < 0) break;
            if (lane == 0) {
                float x  = lg[te];
                float sg = 1.0f / (1.0f + expf(-x));
                if (sg >= 0.05f) outb[te] = 1.0f;
            }
            if (te == 0) break;
            const float* Lr = Lg + (size_t)te * NI;
            float best = -INFINITY; int bi = 0x7fffffff;
            for (int i = lane; i < NI; i += 32) {
                float cc = Lr[i] + trans_t[i * TROW + j];
                if (cc > best) { best = cc; bi = i; }
            }
#pragma unroll
            for (int off = 16; off; off >>= 1) {
                float ov = __shfl_xor_sync(0xffffffffu, best, off);
                int   oi = __shfl_xor_sync(0xffffffffu, bi,   off);
                if (ov > best || (ov == best && oi < bi)) { best = ov; bi = oi; }
            }
            j   = bi;
            pos = 27 + j;
            t   = te - 1;
        }
    }
}

extern "C" void kernel_launch(void* const* d_in, const int* in_sizes, int n_in,
                              void* d_out, int out_size)
{
    (void)in_sizes; (void)n_in; (void)out_size;
    const float* logit = (const float*)d_in[0];
    float* out = (float*)d_out;

    const size_t smem = (size_t)(TROW * TROW + 2 * S_PAD + CHUNK * LR + CHUNK * FR
                                 + 2 * T_LEN + 32) * 4
                      + 32 * 4 + S_PAD;
    cudaFuncSetAttribute(dbn_kernel,
                         cudaFuncAttributeMaxDynamicSharedMemorySize, (int)smem);
    dbn_kernel<<<BATCH, TPB, smem>>>(logit, out);
}